// round 5
// baseline (speedup 1.0000x reference)
#include <cuda_runtime.h>

#define N_NODES_MAX 100000
#define NUM_ANGLE 4
#define D 128

// Scratch: P[a*2+half][node][128]  (precomputed node projections)
__device__ float g_P[(size_t)(2 * NUM_ANGLE) * N_NODES_MAX * D];
// 1 if edge_index is int64, 0 if int32 (JAX x64-disabled canonicalizes to int32)
__device__ int g_idx_is64;

// ---------------------------------------------------------------------------
// Detect index dtype: for int64 indices < n_nodes, every high 32-bit word is 0.
// For an int32 buffer, "high words" are random indices — all-zero is impossible.
// ---------------------------------------------------------------------------
__global__ void detect_idx_kernel(const int* __restrict__ ei32) {
    int is64 = 1;
#pragma unroll
    for (int i = 0; i < 32; i++)
        if (ei32[2 * i + 1] != 0) { is64 = 0; break; }
    g_idx_is64 = is64;
}

// ---------------------------------------------------------------------------
// Precompute: P[g][n][h] = sum_k bond[n][k] * W[a][half*128 + k][h]  (+ bias
// folded into the top half). g = a*2 + half.
// grid = (ceil(n/128), 8), block = 256 (16x16 threads, 8x8 microtile)
// ---------------------------------------------------------------------------
__global__ void __launch_bounds__(256, 2)
precompute_kernel(const float* __restrict__ A,   // bond_feat [n][128]
                  const float* __restrict__ W,   // [4][256][128]
                  const float* __restrict__ bias,// [4][128]
                  int n_nodes) {
    __shared__ float Ast[32][128];   // transposed A chunk: [k][row]
    __shared__ float Bs[32][128];    // W chunk: [k][h]

    const int g = blockIdx.y;              // a*2 + half
    const int a = g >> 1, half = g & 1;
    const float* Bsrc = W + ((size_t)a * 256 + (size_t)half * 128) * D;

    const int node0 = blockIdx.x * 128;
    const int tid = threadIdx.x;
    const int ty = tid >> 4, tx = tid & 15;
    const int r0 = ty * 8, c0 = tx * 8;

    float acc[8][8];
#pragma unroll
    for (int i = 0; i < 8; i++)
#pragma unroll
        for (int j = 0; j < 8; j++) acc[i][j] = 0.f;

    for (int k0 = 0; k0 < D; k0 += 32) {
#pragma unroll
        for (int q = 0; q < 4; q++) {
            int idx = tid + q * 256;          // 0..1023 float4 slots
            int row = idx >> 3;               // 0..127
            int c4  = idx & 7;                // 0..7
            int gr = node0 + row;
            float4 v = make_float4(0.f, 0.f, 0.f, 0.f);
            if (gr < n_nodes)
                v = *(const float4*)(A + (size_t)gr * D + k0 + c4 * 4);
            Ast[c4 * 4 + 0][row] = v.x;
            Ast[c4 * 4 + 1][row] = v.y;
            Ast[c4 * 4 + 2][row] = v.z;
            Ast[c4 * 4 + 3][row] = v.w;
        }
#pragma unroll
        for (int q = 0; q < 4; q++) {
            int idx = tid + q * 256;
            int kk = idx >> 5;                // 0..31
            int c4 = idx & 31;                // 0..31
            *(float4*)(&Bs[kk][c4 * 4]) =
                *(const float4*)(Bsrc + (size_t)(k0 + kk) * D + c4 * 4);
        }
        __syncthreads();

#pragma unroll
        for (int k = 0; k < 32; k++) {
            float af[8], bf[8];
            *(float4*)(af)     = *(const float4*)(&Ast[k][r0]);
            *(float4*)(af + 4) = *(const float4*)(&Ast[k][r0 + 4]);
            *(float4*)(bf)     = *(const float4*)(&Bs[k][c0]);
            *(float4*)(bf + 4) = *(const float4*)(&Bs[k][c0 + 4]);
#pragma unroll
            for (int i = 0; i < 8; i++)
#pragma unroll
                for (int j = 0; j < 8; j++)
                    acc[i][j] = fmaf(af[i], bf[j], acc[i][j]);
        }
        __syncthreads();
    }

    float badd[8] = {0.f, 0.f, 0.f, 0.f, 0.f, 0.f, 0.f, 0.f};
    if (half == 0) {
        *(float4*)(badd)     = *(const float4*)(bias + (size_t)a * D + c0);
        *(float4*)(badd + 4) = *(const float4*)(bias + (size_t)a * D + c0 + 4);
    }

    float* Pg = g_P + (size_t)g * n_nodes * D;
#pragma unroll
    for (int i = 0; i < 8; i++) {
        int gr = node0 + r0 + i;
        if (gr < n_nodes) {
            float4 lo = *(float4*)(&acc[i][0]);
            float4 hi = *(float4*)(&acc[i][4]);
            lo.x += badd[0]; lo.y += badd[1]; lo.z += badd[2]; lo.w += badd[3];
            hi.x += badd[4]; hi.y += badd[5]; hi.z += badd[6]; hi.w += badd[7];
            *(float4*)(Pg + (size_t)gr * D + c0)     = lo;
            *(float4*)(Pg + (size_t)gr * D + c0 + 4) = hi;
        }
    }
}

// ---------------------------------------------------------------------------
// Edge phase: one warp per (edge, head), grid-strided; lane handles 4 features.
//   alpha = tanh(P_top[dst] + P_bot[src]);  out[dst, a*128+h] += alpha * x_j
// ---------------------------------------------------------------------------
__global__ void __launch_bounds__(256)
edge_kernel(const float* __restrict__ bond,
            const void* __restrict__ ei_raw,    // [4][2][E] int32 or int64
            float* __restrict__ out,            // [n][512]
            int n_nodes, int n_edges) {
    const int a = blockIdx.y;
    const int lane = threadIdx.x & 31;
    const int warp_global = blockIdx.x * 8 + (threadIdx.x >> 5);
    const int warp_stride = gridDim.x * 8;
    const int h4 = lane * 4;
    const int is64 = g_idx_is64;

    const size_t row0 = (size_t)a * 2 * n_edges;         // src row offset (elems)
    const size_t row1 = row0 + (size_t)n_edges;          // dst row offset
    const long long* ei64 = (const long long*)ei_raw;
    const int*       ei32 = (const int*)ei_raw;
    const float* Pt = g_P + (size_t)(a * 2 + 0) * n_nodes * D;
    const float* Pb = g_P + (size_t)(a * 2 + 1) * n_nodes * D;

    for (int e = warp_global; e < n_edges; e += warp_stride) {
        int src, dst;
        if (is64) {
            src = (int)__ldg(ei64 + row0 + e);
            dst = (int)__ldg(ei64 + row1 + e);
        } else {
            src = __ldg(ei32 + row0 + e);
            dst = __ldg(ei32 + row1 + e);
        }
        if ((unsigned)src >= (unsigned)n_nodes || (unsigned)dst >= (unsigned)n_nodes)
            continue;  // never taken with sane inputs; turns surprises into rel_err

        const float4 pt = *(const float4*)(Pt + (size_t)dst * D + h4);
        const float4 pb = *(const float4*)(Pb + (size_t)src * D + h4);
        const float4 xj = *(const float4*)(bond + (size_t)src * D + h4);

        float4 m;
        m.x = tanhf(pt.x + pb.x) * xj.x;
        m.y = tanhf(pt.y + pb.y) * xj.y;
        m.z = tanhf(pt.z + pb.z) * xj.z;
        m.w = tanhf(pt.w + pb.w) * xj.w;

        float* optr = out + (size_t)dst * (NUM_ANGLE * D) + a * D + h4;
        asm volatile("red.global.add.v4.f32 [%0], {%1,%2,%3,%4};"
                     :: "l"(optr), "f"(m.x), "f"(m.y), "f"(m.z), "f"(m.w)
                     : "memory");
    }
}

// ---------------------------------------------------------------------------
extern "C" void kernel_launch(void* const* d_in, const int* in_sizes, int n_in,
                              void* d_out, int out_size) {
    const float* bond = (const float*)d_in[0];
    const void*  ei   = d_in[1];
    const float* W    = (const float*)d_in[2];
    const float* b    = (const float*)d_in[3];
    float*       out  = (float*)d_out;

    const int n_nodes = in_sizes[0] / D;                 // 100000
    const int n_edges = in_sizes[1] / (NUM_ANGLE * 2);   // 500000

    // d_out is poisoned; scatter-accumulate needs zeros.
    cudaMemsetAsync(d_out, 0, (size_t)out_size * sizeof(float), 0);

    detect_idx_kernel<<<1, 1>>>((const int*)ei);

    dim3 gg((n_nodes + 127) / 128, 2 * NUM_ANGLE);
    precompute_kernel<<<gg, 256>>>(bond, W, b, n_nodes);

    dim3 ge((n_edges + 7) / 8, NUM_ANGLE);
    edge_kernel<<<ge, 256>>>(bond, ei, out, n_nodes, n_edges);
}

// round 9
// speedup vs baseline: 1.0232x; 1.0232x over previous
#include <cuda_runtime.h>
#include <cstdint>

#define N_NODES_MAX 100000
#define NUM_ANGLE 4
#define D 128

// Scratch: P[a*2+half][node][128]  (precomputed node projections)
__device__ float g_P[(size_t)(2 * NUM_ANGLE) * N_NODES_MAX * D];
// 1 if edge_index is int64, 0 if int32 (JAX x64-disabled canonicalizes to int32)
__device__ int g_idx_is64;

// ---------------------------------------------------------------------------
// Detect index dtype: for int64 indices < n_nodes, every high 32-bit word is 0.
// ---------------------------------------------------------------------------
__global__ void detect_idx_kernel(const int* __restrict__ ei32) {
    int is64 = 1;
#pragma unroll
    for (int i = 0; i < 32; i++)
        if (ei32[2 * i + 1] != 0) { is64 = 0; break; }
    g_idx_is64 = is64;
}

// ---------------------------------------------------------------------------
// Precompute: P[g][n][h] = sum_k bond[n][k] * W[a][half*128 + k][h]  (+ bias
// folded into the top half). g = a*2 + half.
// grid = (ceil(n/128), 8), block = 256 (16x16 threads, 8x8 microtile).
// Inner product uses packed fma.rn.f32x2 (FFMA2): 2 fp32 FMAs / instruction.
// ---------------------------------------------------------------------------
__global__ void __launch_bounds__(256, 2)
precompute_kernel(const float* __restrict__ A,   // bond_feat [n][128]
                  const float* __restrict__ W,   // [4][256][128]
                  const float* __restrict__ bias,// [4][128]
                  int n_nodes) {
    __shared__ float Ast[32][128];   // transposed A chunk: [k][row]
    __shared__ float Bs[32][128];    // W chunk: [k][h]

    const int g = blockIdx.y;              // a*2 + half
    const int a = g >> 1, half = g & 1;
    const float* Bsrc = W + ((size_t)a * 256 + (size_t)half * 128) * D;

    const int node0 = blockIdx.x * 128;
    const int tid = threadIdx.x;
    const int ty = tid >> 4, tx = tid & 15;
    const int r0 = ty * 8, c0 = tx * 8;

    // acc2[i][jp] = packed fp32 pair for columns (c0+2jp, c0+2jp+1)
    unsigned long long acc2[8][4];
#pragma unroll
    for (int i = 0; i < 8; i++)
#pragma unroll
        for (int j = 0; j < 4; j++) acc2[i][j] = 0ull;

    for (int k0 = 0; k0 < D; k0 += 32) {
        // Stage A chunk (128 rows x 32 k) transposed into Ast[k][row]
#pragma unroll
        for (int q = 0; q < 4; q++) {
            int idx = tid + q * 256;          // 0..1023 float4 slots
            int row = idx >> 3;               // 0..127
            int c4  = idx & 7;                // 0..7
            int gr = node0 + row;
            float4 v = make_float4(0.f, 0.f, 0.f, 0.f);
            if (gr < n_nodes)
                v = *(const float4*)(A + (size_t)gr * D + k0 + c4 * 4);
            Ast[c4 * 4 + 0][row] = v.x;
            Ast[c4 * 4 + 1][row] = v.y;
            Ast[c4 * 4 + 2][row] = v.z;
            Ast[c4 * 4 + 3][row] = v.w;
        }
        // Stage B chunk (32 k-rows x 128 h)
#pragma unroll
        for (int q = 0; q < 4; q++) {
            int idx = tid + q * 256;
            int kk = idx >> 5;                // 0..31
            int c4 = idx & 31;                // 0..31
            *(float4*)(&Bs[kk][c4 * 4]) =
                *(const float4*)(Bsrc + (size_t)(k0 + kk) * D + c4 * 4);
        }
        __syncthreads();

#pragma unroll
        for (int k = 0; k < 32; k++) {
            float af[8];
            *(float4*)(af)     = *(const float4*)(&Ast[k][r0]);
            *(float4*)(af + 4) = *(const float4*)(&Ast[k][r0 + 4]);
            // B pairs come pre-packed from smem (32B-aligned)
            ulonglong2 q0 = *(const ulonglong2*)(&Bs[k][c0]);      // cols 0-3
            ulonglong2 q1 = *(const ulonglong2*)(&Bs[k][c0 + 4]);  // cols 4-7
#pragma unroll
            for (int i = 0; i < 8; i++) {
                unsigned long long ai;
                uint32_t au = __float_as_uint(af[i]);
                asm("mov.b64 %0, {%1, %1};" : "=l"(ai) : "r"(au));
                asm("fma.rn.f32x2 %0, %1, %2, %0;" : "+l"(acc2[i][0]) : "l"(ai), "l"(q0.x));
                asm("fma.rn.f32x2 %0, %1, %2, %0;" : "+l"(acc2[i][1]) : "l"(ai), "l"(q0.y));
                asm("fma.rn.f32x2 %0, %1, %2, %0;" : "+l"(acc2[i][2]) : "l"(ai), "l"(q1.x));
                asm("fma.rn.f32x2 %0, %1, %2, %0;" : "+l"(acc2[i][3]) : "l"(ai), "l"(q1.y));
            }
        }
        __syncthreads();
    }

    // Fuse bias into the top-half projection (half==0 pairs with x_i/dst).
    float badd[8] = {0.f, 0.f, 0.f, 0.f, 0.f, 0.f, 0.f, 0.f};
    if (half == 0) {
        *(float4*)(badd)     = *(const float4*)(bias + (size_t)a * D + c0);
        *(float4*)(badd + 4) = *(const float4*)(bias + (size_t)a * D + c0 + 4);
    }

    float* Pg = g_P + (size_t)g * n_nodes * D;
#pragma unroll
    for (int i = 0; i < 8; i++) {
        int gr = node0 + r0 + i;
        if (gr < n_nodes) {
            float out8[8];
#pragma unroll
            for (int jp = 0; jp < 4; jp++) {
                uint32_t lo = (uint32_t)(acc2[i][jp] & 0xffffffffull);
                uint32_t hi = (uint32_t)(acc2[i][jp] >> 32);
                out8[2 * jp]     = __uint_as_float(lo) + badd[2 * jp];
                out8[2 * jp + 1] = __uint_as_float(hi) + badd[2 * jp + 1];
            }
            *(float4*)(Pg + (size_t)gr * D + c0)     = *(float4*)(out8);
            *(float4*)(Pg + (size_t)gr * D + c0 + 4) = *(float4*)(out8 + 4);
        }
    }
}

// ---------------------------------------------------------------------------
// Edge phase: one warp per (edge, head), grid-strided; lane handles 4 features.
//   alpha = tanh(P_top[dst] + P_bot[src]);  out[dst, a*128+h] += alpha * x_j
// ---------------------------------------------------------------------------
__global__ void __launch_bounds__(256)
edge_kernel(const float* __restrict__ bond,
            const void* __restrict__ ei_raw,    // [4][2][E] int32 or int64
            float* __restrict__ out,            // [n][512]
            int n_nodes, int n_edges) {
    const int a = blockIdx.y;
    const int lane = threadIdx.x & 31;
    const int warp_global = blockIdx.x * 8 + (threadIdx.x >> 5);
    const int warp_stride = gridDim.x * 8;
    const int h4 = lane * 4;
    const int is64 = g_idx_is64;

    const size_t row0 = (size_t)a * 2 * n_edges;         // src row offset (elems)
    const size_t row1 = row0 + (size_t)n_edges;          // dst row offset
    const long long* ei64 = (const long long*)ei_raw;
    const int*       ei32 = (const int*)ei_raw;
    const float* Pt = g_P + (size_t)(a * 2 + 0) * n_nodes * D;
    const float* Pb = g_P + (size_t)(a * 2 + 1) * n_nodes * D;

    for (int e = warp_global; e < n_edges; e += warp_stride) {
        int src, dst;
        if (is64) {
            src = (int)__ldg(ei64 + row0 + e);
            dst = (int)__ldg(ei64 + row1 + e);
        } else {
            src = __ldg(ei32 + row0 + e);
            dst = __ldg(ei32 + row1 + e);
        }
        if ((unsigned)src >= (unsigned)n_nodes || (unsigned)dst >= (unsigned)n_nodes)
            continue;  // never taken with sane inputs; turns surprises into rel_err

        const float4 pt = *(const float4*)(Pt + (size_t)dst * D + h4);
        const float4 pb = *(const float4*)(Pb + (size_t)src * D + h4);
        const float4 xj = *(const float4*)(bond + (size_t)src * D + h4);

        float4 m;
        m.x = tanhf(pt.x + pb.x) * xj.x;
        m.y = tanhf(pt.y + pb.y) * xj.y;
        m.z = tanhf(pt.z + pb.z) * xj.z;
        m.w = tanhf(pt.w + pb.w) * xj.w;

        float* optr = out + (size_t)dst * (NUM_ANGLE * D) + a * D + h4;
        asm volatile("red.global.add.v4.f32 [%0], {%1,%2,%3,%4};"
                     :: "l"(optr), "f"(m.x), "f"(m.y), "f"(m.z), "f"(m.w)
                     : "memory");
    }
}

// ---------------------------------------------------------------------------
extern "C" void kernel_launch(void* const* d_in, const int* in_sizes, int n_in,
                              void* d_out, int out_size) {
    const float* bond = (const float*)d_in[0];
    const void*  ei   = d_in[1];
    const float* W    = (const float*)d_in[2];
    const float* b    = (const float*)d_in[3];
    float*       out  = (float*)d_out;

    const int n_nodes = in_sizes[0] / D;                 // 100000
    const int n_edges = in_sizes[1] / (NUM_ANGLE * 2);   // 500000

    // d_out is poisoned; scatter-accumulate needs zeros.
    cudaMemsetAsync(d_out, 0, (size_t)out_size * sizeof(float), 0);

    // Launch order chosen so ncu's skip-5 capture lands on precompute_kernel
    // (4 launches/call incl. memset: launch #6 = call-2's precompute).
    dim3 gg((n_nodes + 127) / 128, 2 * NUM_ANGLE);
    precompute_kernel<<<gg, 256>>>(bond, W, b, n_nodes);

    detect_idx_kernel<<<1, 1>>>((const int*)ei);

    dim3 ge((n_edges + 7) / 8, NUM_ANGLE);
    edge_kernel<<<ge, 256>>>(bond, ei, out, n_nodes, n_edges);
}

// round 10
// speedup vs baseline: 1.0605x; 1.0364x over previous
#include <cuda_runtime.h>
#include <cstdint>

#define N_NODES_MAX 100000
#define NUM_ANGLE 4
#define D 128

// Scratch: P[a*2+half][node][128]  (precomputed node projections)
__device__ float g_P[(size_t)(2 * NUM_ANGLE) * N_NODES_MAX * D];
// 1 if edge_index is int64, 0 if int32 (JAX x64-disabled canonicalizes to int32)
__device__ int g_idx_is64;

// ---------------------------------------------------------------------------
// Detect index dtype: for int64 indices < n_nodes, every high 32-bit word is 0.
// ---------------------------------------------------------------------------
__global__ void detect_idx_kernel(const int* __restrict__ ei32) {
    int is64 = 1;
#pragma unroll
    for (int i = 0; i < 32; i++)
        if (ei32[2 * i + 1] != 0) { is64 = 0; break; }
    g_idx_is64 = is64;
}

// ---------------------------------------------------------------------------
// Precompute: P[g][n][h] = sum_k bond[n][k] * W[a][half*128 + k][h]  (+ bias
// folded into the top half). g = a*2 + half.
// grid = (ceil(n/128), 8), block = 256 (16x16 threads, 8x8 microtile).
// fma.rn.f32x2 inner product; bank-conflict-free smem layouts:
//   Ast[32][128], staged with warp-consecutive rows (32 distinct banks/inst)
//   Bs chunked: 8-float chunks at 12-float (48B) stride -> 2-way min on reads
// ---------------------------------------------------------------------------
__global__ void __launch_bounds__(256, 2)
precompute_kernel(const float* __restrict__ A,   // bond_feat [n][128]
                  const float* __restrict__ W,   // [4][256][128]
                  const float* __restrict__ bias,// [4][128]
                  int n_nodes) {
    __shared__ float Ast[32][128];        // [k][row], stride 128
    __shared__ float Bs[32 * 16 * 12];    // chunk (k,c): floats at (k*16+c)*12

    const int g = blockIdx.y;              // a*2 + half
    const int a = g >> 1, half = g & 1;
    const float* Bsrc = W + ((size_t)a * 256 + (size_t)half * 128) * D;

    const int node0 = blockIdx.x * 128;
    const int tid = threadIdx.x;
    const int ty = tid >> 4, tx = tid & 15;
    const int r0 = ty * 8;
    const int c0 = tx * 8;

    // acc2[i][jp] = packed fp32 pair for columns (c0+2jp, c0+2jp+1)
    unsigned long long acc2[8][4];
#pragma unroll
    for (int i = 0; i < 8; i++)
#pragma unroll
        for (int j = 0; j < 4; j++) acc2[i][j] = 0ull;

    for (int k0 = 0; k0 < D; k0 += 32) {
        // Stage A chunk transposed. Mapping: row fine-grained over tid so each
        // warp's 32 scalar STS hit 32 consecutive rows = 32 distinct banks.
#pragma unroll
        for (int q = 0; q < 4; q++) {
            int idx = tid + q * 256;          // 0..1023
            int row = idx & 127;              // 0..127
            int c4  = idx >> 7;               // 0..7 (float4 within 32 k)
            int gr = node0 + row;
            float4 v = make_float4(0.f, 0.f, 0.f, 0.f);
            if (gr < n_nodes)
                v = *(const float4*)(A + (size_t)gr * D + k0 + c4 * 4);
            Ast[c4 * 4 + 0][row] = v.x;
            Ast[c4 * 4 + 1][row] = v.y;
            Ast[c4 * 4 + 2][row] = v.z;
            Ast[c4 * 4 + 3][row] = v.w;
        }
        // Stage B chunk (32 k-rows x 128 h) into chunked 48B-stride layout
#pragma unroll
        for (int q = 0; q < 4; q++) {
            int idx = tid + q * 256;          // 0..1023 float4 slots
            int kk = idx >> 5;                // 0..31
            int c4 = idx & 31;                // float4 col 0..31
            float4 v = *(const float4*)(Bsrc + (size_t)(k0 + kk) * D + c4 * 4);
            // chunk = c4>>1 (8-float chunk), half-of-chunk = c4&1
            *(float4*)(&Bs[((kk * 16 + (c4 >> 1)) * 12) + (c4 & 1) * 4]) = v;
        }
        __syncthreads();

#pragma unroll
        for (int k = 0; k < 32; k++) {
            float af[8];
            *(float4*)(af)     = *(const float4*)(&Ast[k][r0]);
            *(float4*)(af + 4) = *(const float4*)(&Ast[k][r0 + 4]);
            const float* bchunk = &Bs[(k * 16 + tx) * 12];
            ulonglong2 q0 = *(const ulonglong2*)(bchunk);      // cols 0-3
            ulonglong2 q1 = *(const ulonglong2*)(bchunk + 4);  // cols 4-7
#pragma unroll
            for (int i = 0; i < 8; i++) {
                unsigned long long ai;
                uint32_t au = __float_as_uint(af[i]);
                asm("mov.b64 %0, {%1, %1};" : "=l"(ai) : "r"(au));
                asm("fma.rn.f32x2 %0, %1, %2, %0;" : "+l"(acc2[i][0]) : "l"(ai), "l"(q0.x));
                asm("fma.rn.f32x2 %0, %1, %2, %0;" : "+l"(acc2[i][1]) : "l"(ai), "l"(q0.y));
                asm("fma.rn.f32x2 %0, %1, %2, %0;" : "+l"(acc2[i][2]) : "l"(ai), "l"(q1.x));
                asm("fma.rn.f32x2 %0, %1, %2, %0;" : "+l"(acc2[i][3]) : "l"(ai), "l"(q1.y));
            }
        }
        __syncthreads();
    }

    // Fuse bias into the top-half projection (half==0 pairs with x_i/dst).
    float badd[8] = {0.f, 0.f, 0.f, 0.f, 0.f, 0.f, 0.f, 0.f};
    if (half == 0) {
        *(float4*)(badd)     = *(const float4*)(bias + (size_t)a * D + c0);
        *(float4*)(badd + 4) = *(const float4*)(bias + (size_t)a * D + c0 + 4);
    }

    float* Pg = g_P + (size_t)g * n_nodes * D;
#pragma unroll
    for (int i = 0; i < 8; i++) {
        int gr = node0 + r0 + i;
        if (gr < n_nodes) {
            float out8[8];
#pragma unroll
            for (int jp = 0; jp < 4; jp++) {
                uint32_t lo = (uint32_t)(acc2[i][jp] & 0xffffffffull);
                uint32_t hi = (uint32_t)(acc2[i][jp] >> 32);
                out8[2 * jp]     = __uint_as_float(lo) + badd[2 * jp];
                out8[2 * jp + 1] = __uint_as_float(hi) + badd[2 * jp + 1];
            }
            *(float4*)(Pg + (size_t)gr * D + c0)     = *(float4*)(out8);
            *(float4*)(Pg + (size_t)gr * D + c0 + 4) = *(float4*)(out8 + 4);
        }
    }
}

// ---------------------------------------------------------------------------
// Edge phase: one warp per (edge, head), grid-strided; lane handles 4 features.
//   alpha = tanh(P_top[dst] + P_bot[src]);  out[dst, a*128+h] += alpha * x_j
// ---------------------------------------------------------------------------
__global__ void __launch_bounds__(256)
edge_kernel(const float* __restrict__ bond,
            const void* __restrict__ ei_raw,    // [4][2][E] int32 or int64
            float* __restrict__ out,            // [n][512]
            int n_nodes, int n_edges) {
    const int a = blockIdx.y;
    const int lane = threadIdx.x & 31;
    const int warp_global = blockIdx.x * 8 + (threadIdx.x >> 5);
    const int warp_stride = gridDim.x * 8;
    const int h4 = lane * 4;
    const int is64 = g_idx_is64;

    const size_t row0 = (size_t)a * 2 * n_edges;         // src row offset (elems)
    const size_t row1 = row0 + (size_t)n_edges;          // dst row offset
    const long long* ei64 = (const long long*)ei_raw;
    const int*       ei32 = (const int*)ei_raw;
    const float* Pt = g_P + (size_t)(a * 2 + 0) * n_nodes * D;
    const float* Pb = g_P + (size_t)(a * 2 + 1) * n_nodes * D;

    for (int e = warp_global; e < n_edges; e += warp_stride) {
        int src, dst;
        if (is64) {
            src = (int)__ldg(ei64 + row0 + e);
            dst = (int)__ldg(ei64 + row1 + e);
        } else {
            src = __ldg(ei32 + row0 + e);
            dst = __ldg(ei32 + row1 + e);
        }
        if ((unsigned)src >= (unsigned)n_nodes || (unsigned)dst >= (unsigned)n_nodes)
            continue;  // never taken with sane inputs; turns surprises into rel_err

        const float4 pt = *(const float4*)(Pt + (size_t)dst * D + h4);
        const float4 pb = *(const float4*)(Pb + (size_t)src * D + h4);
        const float4 xj = *(const float4*)(bond + (size_t)src * D + h4);

        float4 m;
        m.x = tanhf(pt.x + pb.x) * xj.x;
        m.y = tanhf(pt.y + pb.y) * xj.y;
        m.z = tanhf(pt.z + pb.z) * xj.z;
        m.w = tanhf(pt.w + pb.w) * xj.w;

        float* optr = out + (size_t)dst * (NUM_ANGLE * D) + a * D + h4;
        asm volatile("red.global.add.v4.f32 [%0], {%1,%2,%3,%4};"
                     :: "l"(optr), "f"(m.x), "f"(m.y), "f"(m.z), "f"(m.w)
                     : "memory");
    }
}

// ---------------------------------------------------------------------------
extern "C" void kernel_launch(void* const* d_in, const int* in_sizes, int n_in,
                              void* d_out, int out_size) {
    const float* bond = (const float*)d_in[0];
    const void*  ei   = d_in[1];
    const float* W    = (const float*)d_in[2];
    const float* b    = (const float*)d_in[3];
    float*       out  = (float*)d_out;

    const int n_nodes = in_sizes[0] / D;                 // 100000
    const int n_edges = in_sizes[1] / (NUM_ANGLE * 2);   // 500000

    // d_out is poisoned; scatter-accumulate needs zeros.
    cudaMemsetAsync(d_out, 0, (size_t)out_size * sizeof(float), 0);

    // Launch order chosen so ncu's skip-5 capture lands on precompute_kernel
    // (4 launches/call incl. memset: launch #6 = call-2's precompute).
    dim3 gg((n_nodes + 127) / 128, 2 * NUM_ANGLE);
    precompute_kernel<<<gg, 256>>>(bond, W, b, n_nodes);

    detect_idx_kernel<<<1, 1>>>((const int*)ei);

    dim3 ge((n_edges + 7) / 8, NUM_ANGLE);
    edge_kernel<<<ge, 256>>>(bond, ei, out, n_nodes, n_edges);
}